// round 9
// baseline (speedup 1.0000x reference)
#include <cuda_runtime.h>
#include <cstdint>

// Problem dims (fixed for this problem instance)
#define BB 1024
#define DD 512
#define HH 512
#define AA 18
#define TT 64

// scratch (device globals: no alloc allowed)
__device__ float g_h[BB * HH];
__device__ int g_task[BB];

// ---------------------------------------------------------------------------
// task_id dtype normalizer. Detect int64-vs-int32 at runtime:
//   int64 layout: u32 words [v0,0, v1,0, ...]  (hi words all 0 since v<64)
//   int32 layout: u32 words [v0, v1, ...]
// (Bench evidence R5 vs R6: data is int32 — x64 disabled downgraded jnp.int64.)
// ---------------------------------------------------------------------------
__global__ __launch_bounds__(512) void normalize_task_kernel(
    const unsigned int* __restrict__ raw)
{
    const int t = threadIdx.x;  // 0..511
    const int is64 = __syncthreads_and(raw[2 * t + 1] == 0u);
    for (int b = t; b < BB; b += 512)
        g_task[b] = is64 ? (int)raw[2 * b] : (int)raw[b];
}

// ---------------------------------------------------------------------------
// fc1: h[b, :] = relu(xs[b, :] @ w1[task[b]] + b1[task[b]])
// grid (T, 2): block = (task, h-tile of 256). 128 threads, each owns 2 h cols.
// ---------------------------------------------------------------------------
__global__ __launch_bounds__(128) void fc1_kernel(
    const float* __restrict__ xs,
    const float* __restrict__ w1,
    const float* __restrict__ b1,
    float* __restrict__ hout)
{
    const int t = blockIdx.x;
    const int h0 = blockIdx.y * 256;
    const int tid = threadIdx.x;

    __shared__ int s_idx[BB];
    __shared__ int s_cnt;
    __shared__ float s_x[16][DD];

    if (tid == 0) s_cnt = 0;
    __syncthreads();
    for (int b = tid; b < BB; b += 128) {
        if (g_task[b] == t) {
            int p = atomicAdd(&s_cnt, 1);
            s_idx[p] = b;
        }
    }
    __syncthreads();
    const int cnt = s_cnt;
    if (cnt == 0) return;

    const float* wbase = w1 + (size_t)t * DD * HH + h0 + tid * 2;
    const float2 bias = *(const float2*)(b1 + (size_t)t * HH + h0 + tid * 2);

    for (int c0 = 0; c0 < cnt; c0 += 16) {
        const int m = min(16, cnt - c0);
        for (int r = 0; r < 16; r++) {
            if (r < m) {
                const float* src = xs + (size_t)s_idx[c0 + r] * DD;
                for (int d = tid; d < DD; d += 128) s_x[r][d] = src[d];
            } else {
                for (int d = tid; d < DD; d += 128) s_x[r][d] = 0.0f;
            }
        }
        __syncthreads();

        float2 acc[16];
        #pragma unroll
        for (int r = 0; r < 16; r++) { acc[r].x = 0.0f; acc[r].y = 0.0f; }

        #pragma unroll 4
        for (int d = 0; d < DD; d++) {
            const float2 w = *(const float2*)(wbase + (size_t)d * HH);
            #pragma unroll
            for (int r = 0; r < 16; r++) {
                const float x = s_x[r][d];
                acc[r].x = fmaf(x, w.x, acc[r].x);
                acc[r].y = fmaf(x, w.y, acc[r].y);
            }
        }

        for (int r = 0; r < m; r++) {
            const int b = s_idx[c0 + r];
            float2 v;
            v.x = fmaxf(acc[r].x + bias.x, 0.0f);
            v.y = fmaxf(acc[r].y + bias.y, 0.0f);
            *(float2*)(hout + (size_t)b * HH + h0 + tid * 2) = v;
        }
        __syncthreads();
    }
}

// ---------------------------------------------------------------------------
// JAX Threefry-2x32 (key = (0, 1) for jax.random.key(1))
// ---------------------------------------------------------------------------
__device__ __forceinline__ uint32_t rotl32(uint32_t x, int r) {
    return (x << r) | (x >> (32 - r));
}

__device__ uint2 threefry2x32(uint32_t k0, uint32_t k1, uint32_t x0, uint32_t x1)
{
    const uint32_t ks0 = k0, ks1 = k1, ks2 = k0 ^ k1 ^ 0x1BD11BDAu;
    x0 += ks0; x1 += ks1;
    x0 += x1; x1 = rotl32(x1, 13); x1 ^= x0;
    x0 += x1; x1 = rotl32(x1, 15); x1 ^= x0;
    x0 += x1; x1 = rotl32(x1, 26); x1 ^= x0;
    x0 += x1; x1 = rotl32(x1,  6); x1 ^= x0;
    x0 += ks1; x1 += ks2 + 1u;
    x0 += x1; x1 = rotl32(x1, 17); x1 ^= x0;
    x0 += x1; x1 = rotl32(x1, 29); x1 ^= x0;
    x0 += x1; x1 = rotl32(x1, 16); x1 ^= x0;
    x0 += x1; x1 = rotl32(x1, 24); x1 ^= x0;
    x0 += ks2; x1 += ks0 + 2u;
    x0 += x1; x1 = rotl32(x1, 13); x1 ^= x0;
    x0 += x1; x1 = rotl32(x1, 15); x1 ^= x0;
    x0 += x1; x1 = rotl32(x1, 26); x1 ^= x0;
    x0 += x1; x1 = rotl32(x1,  6); x1 ^= x0;
    x0 += ks0; x1 += ks1 + 3u;
    x0 += x1; x1 = rotl32(x1, 17); x1 ^= x0;
    x0 += x1; x1 = rotl32(x1, 29); x1 ^= x0;
    x0 += x1; x1 = rotl32(x1, 16); x1 ^= x0;
    x0 += x1; x1 = rotl32(x1, 24); x1 ^= x0;
    x0 += ks1; x1 += ks2 + 4u;
    x0 += x1; x1 = rotl32(x1, 13); x1 ^= x0;
    x0 += x1; x1 = rotl32(x1, 15); x1 ^= x0;
    x0 += x1; x1 = rotl32(x1, 26); x1 ^= x0;
    x0 += x1; x1 = rotl32(x1,  6); x1 ^= x0;
    x0 += ks2; x1 += ks0 + 5u;
    return make_uint2(x0, x1);
}

// JAX PARTITIONABLE threefry random_bits (default since jax 0.4.36), 32-bit:
//   counts = iota(u64, N); per element i:
//   (b1, b2) = threefry2x32(k0, k1, hi(i)=0, lo(i)=i)
//   bits[i]  = b1 ^ b2        <-- sub-64-bit widths XOR the two output words
__device__ __forceinline__ uint32_t jax_random_bits(uint32_t i)
{
    uint2 r = threefry2x32(0u, 1u, 0u, i);
    return r.x ^ r.y;
}

// ---------------------------------------------------------------------------
// fc2 + log_softmax + gumbel categorical + log_prob + entropy
// one block per task (w2[t] staged in smem), one warp per sample.
// ---------------------------------------------------------------------------
__global__ __launch_bounds__(256) void fc2_kernel(
    const float* __restrict__ w2,
    const float* __restrict__ b2,
    const float* __restrict__ hin,
    float* __restrict__ out)
{
    const int t = blockIdx.x;
    const int tid = threadIdx.x;

    __shared__ float s_w[HH * AA];   // 36 KB
    __shared__ float s_b[AA];
    __shared__ int s_idx[BB];
    __shared__ int s_cnt;

    if (tid == 0) s_cnt = 0;
    const float* w2t = w2 + (size_t)t * HH * AA;
    for (int i = tid; i < HH * AA; i += 256) s_w[i] = w2t[i];
    if (tid < AA) s_b[tid] = b2[t * AA + tid];
    __syncthreads();
    for (int b = tid; b < BB; b += 256) {
        if (g_task[b] == t) {
            int p = atomicAdd(&s_cnt, 1);
            s_idx[p] = b;
        }
    }
    __syncthreads();
    const int cnt = s_cnt;

    const int warp = tid >> 5;
    const int l = tid & 31;

    for (int s = warp; s < cnt; s += 8) {
        const int b = s_idx[s];
        float hreg[16];
        #pragma unroll
        for (int i = 0; i < 16; i++) hreg[i] = hin[(size_t)b * HH + i * 32 + l];

        float logit = -INFINITY;  // lane a<18 holds logits[a]
        #pragma unroll
        for (int a = 0; a < AA; a++) {
            float p = 0.0f;
            #pragma unroll
            for (int i = 0; i < 16; i++)
                p = fmaf(hreg[i], s_w[(i * 32 + l) * AA + a], p);
            #pragma unroll
            for (int off = 16; off > 0; off >>= 1)
                p += __shfl_xor_sync(0xffffffffu, p, off);
            if (l == a) logit = p + s_b[a];
        }

        // log_softmax
        float mx = logit;
        #pragma unroll
        for (int off = 16; off > 0; off >>= 1)
            mx = fmaxf(mx, __shfl_xor_sync(0xffffffffu, mx, off));
        float ex = (l < AA) ? expf(logit - mx) : 0.0f;
        float sum = ex;
        #pragma unroll
        for (int off = 16; off > 0; off >>= 1)
            sum += __shfl_xor_sync(0xffffffffu, sum, off);
        const float lse = mx + logf(sum);
        const float logp = logit - lse;

        // entropy = -sum p*logp
        float ent = (l < AA) ? (-expf(logp) * logp) : 0.0f;
        #pragma unroll
        for (int off = 16; off > 0; off >>= 1)
            ent += __shfl_xor_sync(0xffffffffu, ent, off);

        // gumbel noise (JAX partitionable threefry, XOR convention)
        float y = -INFINITY;
        if (l < AA) {
            const uint32_t bits = jax_random_bits((uint32_t)(b * AA + l));
            const float f = __uint_as_float((bits >> 9) | 0x3f800000u) - 1.0f;
            const float TINY = 1.17549435e-38f;
            const float u = fmaxf(TINY, f * (1.0f - TINY) + TINY);
            const float g = -logf(-logf(u));
            y = logit + g;
        }
        // argmax with first-index tiebreak
        int bi = l;
        #pragma unroll
        for (int off = 16; off > 0; off >>= 1) {
            const float oy = __shfl_xor_sync(0xffffffffu, y, off);
            const int ob = __shfl_xor_sync(0xffffffffu, bi, off);
            if (oy > y || (oy == y && ob < bi)) { y = oy; bi = ob; }
        }
        const float lp_action = __shfl_sync(0xffffffffu, logp, bi);

        if (l == 0) {
            out[b] = (float)bi;
            out[BB + b] = lp_action;
            out[2 * BB + b] = ent;
        }
    }
}

extern "C" void kernel_launch(void* const* d_in, const int* in_sizes, int n_in,
                              void* d_out, int out_size)
{
    // Map inputs by element count (all distinct) — immune to metadata ordering.
    const float* xs = nullptr;
    const unsigned int* task_raw = nullptr;
    const float* w1 = nullptr;
    const float* b1 = nullptr;
    const float* w2 = nullptr;
    const float* b2 = nullptr;
    for (int i = 0; i < n_in; i++) {
        switch (in_sizes[i]) {
            case BB * DD:        xs = (const float*)d_in[i]; break;        // 524288
            case BB:             task_raw = (const unsigned int*)d_in[i]; break; // 1024
            case TT * DD * HH:   w1 = (const float*)d_in[i]; break;        // 16777216
            case TT * HH:        b1 = (const float*)d_in[i]; break;        // 32768
            case TT * HH * AA:   w2 = (const float*)d_in[i]; break;        // 589824
            case TT * AA:        b2 = (const float*)d_in[i]; break;        // 1152
            default: break;
        }
    }
    float* out = (float*)d_out;

    float* hbuf;
    cudaGetSymbolAddress((void**)&hbuf, g_h);

    normalize_task_kernel<<<1, 512>>>(task_raw);
    dim3 g1(TT, 2);
    fc1_kernel<<<g1, 128>>>(xs, w1, b1, hbuf);
    fc2_kernel<<<TT, 256>>>(w2, b2, hbuf, out);
}

// round 13
// speedup vs baseline: 2.4224x; 2.4224x over previous
#include <cuda_runtime.h>
#include <cstdint>

#define BB 1024
#define DD 512
#define HH 512
#define AA 18
#define TT 64

// scratch (device globals: no alloc allowed). Partial fc1 sums: d-half 0 / 1.
__device__ float g_hA[BB * HH];
__device__ float g_hB[BB * HH];

// ---------------------------------------------------------------------------
// Shared helper: detect task dtype (int64 downgraded to int32 by x64-disabled
// JAX — confirmed int32 by R5/R6 bench evidence, but keep runtime detection)
// and build this task's sample list in smem. Caller provides s_idx/s_cnt.
// ---------------------------------------------------------------------------
__device__ __forceinline__ int build_task_list(
    const unsigned int* __restrict__ raw, int t, int tid, int nthreads,
    int* s_idx, int* s_cnt)
{
    if (tid == 0) *s_cnt = 0;
    bool odd_zero = true;
    for (int i = tid; i < BB / 2; i += nthreads)
        odd_zero &= (raw[2 * i + 1] == 0u);
    const int is64 = __syncthreads_and(odd_zero);
    for (int b = tid; b < BB; b += nthreads) {
        const int tv = is64 ? (int)raw[2 * b] : (int)raw[b];
        if (tv == t) s_idx[atomicAdd(s_cnt, 1)] = b;
    }
    __syncthreads();
    return *s_cnt;
}

// ---------------------------------------------------------------------------
// fc1 partial: grid (T, 2 h-tiles of 256, 2 d-halves of 256). 128 threads.
// Thread owns 2 h cols x 16 sample rows. Weight float2 stream with 8-deep
// register prefetch (MLP=8). d-half 0 folds in the bias; relu happens in fc2.
// ---------------------------------------------------------------------------
__global__ __launch_bounds__(128) void fc1_kernel(
    const float* __restrict__ xs,
    const unsigned int* __restrict__ task_raw,
    const float* __restrict__ w1,
    const float* __restrict__ b1,
    float* __restrict__ gA,
    float* __restrict__ gB)
{
    const int t = blockIdx.x;
    const int h0 = blockIdx.y * 256;
    const int d0 = blockIdx.z * 256;
    const int tid = threadIdx.x;

    // NOTE: s_x must be 16B-aligned — it is accessed through float2* casts.
    // (R12 failure: shared float[] is only 4B-aligned by default; following
    // s_idx+s_cnt it landed at offset 516 -> misaligned address trap.)
    __shared__ __align__(16) float s_x[16][256];
    __shared__ int s_idx[128];
    __shared__ int s_cnt;

    const int cnt = build_task_list(task_raw, t, tid, 128, s_idx, &s_cnt);
    if (cnt == 0) return;

    const float* wbase = w1 + (size_t)t * DD * HH + (size_t)d0 * HH + h0 + tid * 2;
    float2 bias = make_float2(0.0f, 0.0f);
    if (d0 == 0)
        bias = *(const float2*)(b1 + (size_t)t * HH + h0 + tid * 2);
    float* gout = (d0 == 0) ? gA : gB;

    for (int c0 = 0; c0 < cnt; c0 += 16) {
        const int m = min(16, cnt - c0);
        // stage x rows for this d-half: 256 floats per row, float2 per thread
        #pragma unroll
        for (int r = 0; r < 16; r++) {
            float2 v = make_float2(0.0f, 0.0f);
            if (r < m)
                v = *(const float2*)(xs + (size_t)s_idx[c0 + r] * DD + d0 + tid * 2);
            *(float2*)&s_x[r][tid * 2] = v;
        }
        __syncthreads();

        float2 acc[16];
        #pragma unroll
        for (int r = 0; r < 16; r++) { acc[r].x = 0.0f; acc[r].y = 0.0f; }

        // software-pipelined weight stream: 8 float2 loads in flight
        float2 wreg[8];
        #pragma unroll
        for (int k = 0; k < 8; k++)
            wreg[k] = *(const float2*)(wbase + (size_t)k * HH);

        for (int d = 0; d < 256; d += 8) {
            float2 wc[8];
            #pragma unroll
            for (int k = 0; k < 8; k++) wc[k] = wreg[k];
            if (d + 8 < 256) {
                #pragma unroll
                for (int k = 0; k < 8; k++)
                    wreg[k] = *(const float2*)(wbase + (size_t)(d + 8 + k) * HH);
            }
            #pragma unroll
            for (int k = 0; k < 8; k++) {
                #pragma unroll
                for (int r = 0; r < 16; r++) {
                    const float x = s_x[r][d + k];
                    acc[r].x = fmaf(x, wc[k].x, acc[r].x);
                    acc[r].y = fmaf(x, wc[k].y, acc[r].y);
                }
            }
        }

        for (int r = 0; r < m; r++) {
            const int b = s_idx[c0 + r];
            float2 v;
            v.x = acc[r].x + bias.x;
            v.y = acc[r].y + bias.y;
            *(float2*)(gout + (size_t)b * HH + h0 + tid * 2) = v;
        }
        __syncthreads();
    }
}

// ---------------------------------------------------------------------------
// JAX Threefry-2x32, partitionable convention (verified R9):
// bits[i] = w0 ^ w1 of threefry2x32(k0=0, k1=1, x0=0, x1=i)
// ---------------------------------------------------------------------------
__device__ __forceinline__ uint32_t rotl32(uint32_t x, int r) {
    return (x << r) | (x >> (32 - r));
}

__device__ uint2 threefry2x32(uint32_t k0, uint32_t k1, uint32_t x0, uint32_t x1)
{
    const uint32_t ks0 = k0, ks1 = k1, ks2 = k0 ^ k1 ^ 0x1BD11BDAu;
    x0 += ks0; x1 += ks1;
    x0 += x1; x1 = rotl32(x1, 13); x1 ^= x0;
    x0 += x1; x1 = rotl32(x1, 15); x1 ^= x0;
    x0 += x1; x1 = rotl32(x1, 26); x1 ^= x0;
    x0 += x1; x1 = rotl32(x1,  6); x1 ^= x0;
    x0 += ks1; x1 += ks2 + 1u;
    x0 += x1; x1 = rotl32(x1, 17); x1 ^= x0;
    x0 += x1; x1 = rotl32(x1, 29); x1 ^= x0;
    x0 += x1; x1 = rotl32(x1, 16); x1 ^= x0;
    x0 += x1; x1 = rotl32(x1, 24); x1 ^= x0;
    x0 += ks2; x1 += ks0 + 2u;
    x0 += x1; x1 = rotl32(x1, 13); x1 ^= x0;
    x0 += x1; x1 = rotl32(x1, 15); x1 ^= x0;
    x0 += x1; x1 = rotl32(x1, 26); x1 ^= x0;
    x0 += x1; x1 = rotl32(x1,  6); x1 ^= x0;
    x0 += ks0; x1 += ks1 + 3u;
    x0 += x1; x1 = rotl32(x1, 17); x1 ^= x0;
    x0 += x1; x1 = rotl32(x1, 29); x1 ^= x0;
    x0 += x1; x1 = rotl32(x1, 16); x1 ^= x0;
    x0 += x1; x1 = rotl32(x1, 24); x1 ^= x0;
    x0 += ks1; x1 += ks2 + 4u;
    x0 += x1; x1 = rotl32(x1, 13); x1 ^= x0;
    x0 += x1; x1 = rotl32(x1, 15); x1 ^= x0;
    x0 += x1; x1 = rotl32(x1, 26); x1 ^= x0;
    x0 += x1; x1 = rotl32(x1,  6); x1 ^= x0;
    x0 += ks2; x1 += ks0 + 5u;
    return make_uint2(x0, x1);
}

__device__ __forceinline__ uint32_t jax_random_bits(uint32_t i)
{
    uint2 r = threefry2x32(0u, 1u, 0u, i);
    return r.x ^ r.y;
}

// ---------------------------------------------------------------------------
// fc2 + log_softmax + gumbel categorical + log_prob + entropy.
// One block per task, one warp per sample. h = relu(hA + hB) on read.
// ---------------------------------------------------------------------------
__global__ __launch_bounds__(256) void fc2_kernel(
    const unsigned int* __restrict__ task_raw,
    const float* __restrict__ w2,
    const float* __restrict__ b2,
    const float* __restrict__ hA,
    const float* __restrict__ hB,
    float* __restrict__ out)
{
    const int t = blockIdx.x;
    const int tid = threadIdx.x;

    __shared__ __align__(16) float s_w[HH * AA];   // 36 KB
    __shared__ float s_b[AA];
    __shared__ int s_idx[128];
    __shared__ int s_cnt;

    // stage w2[t] while list builds
    const float* w2t = w2 + (size_t)t * HH * AA;
    for (int i = tid; i < HH * AA; i += 256) s_w[i] = w2t[i];
    if (tid < AA) s_b[tid] = b2[t * AA + tid];
    const int cnt = build_task_list(task_raw, t, tid, 256, s_idx, &s_cnt);

    const int warp = tid >> 5;
    const int l = tid & 31;

    for (int s = warp; s < cnt; s += 8) {
        const int b = s_idx[s];
        float hreg[16];
        #pragma unroll
        for (int i = 0; i < 16; i++) {
            const size_t off = (size_t)b * HH + i * 32 + l;
            hreg[i] = fmaxf(hA[off] + hB[off], 0.0f);
        }

        float logit = -INFINITY;  // lane a<18 holds logits[a]
        #pragma unroll
        for (int a = 0; a < AA; a++) {
            float p = 0.0f;
            #pragma unroll
            for (int i = 0; i < 16; i++)
                p = fmaf(hreg[i], s_w[(i * 32 + l) * AA + a], p);
            #pragma unroll
            for (int off = 16; off > 0; off >>= 1)
                p += __shfl_xor_sync(0xffffffffu, p, off);
            if (l == a) logit = p + s_b[a];
        }

        // log_softmax
        float mx = logit;
        #pragma unroll
        for (int off = 16; off > 0; off >>= 1)
            mx = fmaxf(mx, __shfl_xor_sync(0xffffffffu, mx, off));
        float ex = (l < AA) ? expf(logit - mx) : 0.0f;
        float sum = ex;
        #pragma unroll
        for (int off = 16; off > 0; off >>= 1)
            sum += __shfl_xor_sync(0xffffffffu, sum, off);
        const float lse = mx + logf(sum);
        const float logp = logit - lse;

        // entropy
        float ent = (l < AA) ? (-expf(logp) * logp) : 0.0f;
        #pragma unroll
        for (int off = 16; off > 0; off >>= 1)
            ent += __shfl_xor_sync(0xffffffffu, ent, off);

        // gumbel noise (JAX partitionable threefry, XOR convention)
        float y = -INFINITY;
        if (l < AA) {
            const uint32_t bits = jax_random_bits((uint32_t)(b * AA + l));
            const float f = __uint_as_float((bits >> 9) | 0x3f800000u) - 1.0f;
            const float TINY = 1.17549435e-38f;
            const float u = fmaxf(TINY, f * (1.0f - TINY) + TINY);
            const float g = -logf(-logf(u));
            y = logit + g;
        }
        // argmax, first-index tiebreak
        int bi = l;
        #pragma unroll
        for (int off = 16; off > 0; off >>= 1) {
            const float oy = __shfl_xor_sync(0xffffffffu, y, off);
            const int ob = __shfl_xor_sync(0xffffffffu, bi, off);
            if (oy > y || (oy == y && ob < bi)) { y = oy; bi = ob; }
        }
        const float lp_action = __shfl_sync(0xffffffffu, logp, bi);

        if (l == 0) {
            out[b] = (float)bi;
            out[BB + b] = lp_action;
            out[2 * BB + b] = ent;
        }
    }
}

extern "C" void kernel_launch(void* const* d_in, const int* in_sizes, int n_in,
                              void* d_out, int out_size)
{
    // Map inputs by element count (all distinct) — immune to metadata ordering.
    const float* xs = nullptr;
    const unsigned int* task_raw = nullptr;
    const float* w1 = nullptr;
    const float* b1 = nullptr;
    const float* w2 = nullptr;
    const float* b2 = nullptr;
    for (int i = 0; i < n_in; i++) {
        switch (in_sizes[i]) {
            case BB * DD:        xs = (const float*)d_in[i]; break;
            case BB:             task_raw = (const unsigned int*)d_in[i]; break;
            case TT * DD * HH:   w1 = (const float*)d_in[i]; break;
            case TT * HH:        b1 = (const float*)d_in[i]; break;
            case TT * HH * AA:   w2 = (const float*)d_in[i]; break;
            case TT * AA:        b2 = (const float*)d_in[i]; break;
            default: break;
        }
    }
    float* out = (float*)d_out;

    float *hA, *hB;
    cudaGetSymbolAddress((void**)&hA, g_hA);
    cudaGetSymbolAddress((void**)&hB, g_hB);

    dim3 g1(TT, 2, 2);
    fc1_kernel<<<g1, 128>>>(xs, task_raw, w1, b1, hA, hB);
    fc2_kernel<<<TT, 256>>>(task_raw, w2, b2, hA, hB, out);
}

// round 16
// speedup vs baseline: 2.4974x; 1.0310x over previous
#include <cuda_runtime.h>
#include <cstdint>

#define BB 1024
#define DD 512
#define HH 512
#define AA 18
#define TT 64

// scratch (device globals: no alloc allowed). Partial fc1 sums: d-half 0 / 1.
__device__ float g_hA[BB * HH];
__device__ float g_hB[BB * HH];

// ---------------------------------------------------------------------------
// task list builder with runtime int64/int32 detection (data is int32 per
// R5/R6 evidence; detection kept as a guard). Optional sample filter mask:
// keep b only if (b & bmask) == bval. CRITICAL (R14/R15 lesson): any split of
// samples across blocks must partition by a property of b itself — atomicAdd
// list order differs per block, so position-based splits drop samples.
// ---------------------------------------------------------------------------
__device__ __forceinline__ int build_task_list(
    const unsigned int* __restrict__ raw, int t, int tid, int nthreads,
    int bmask, int bval, int* s_idx, int* s_cnt)
{
    if (tid == 0) *s_cnt = 0;
    bool odd_zero = true;
    for (int i = tid; i < BB / 2; i += nthreads)
        odd_zero &= (raw[2 * i + 1] == 0u);
    const int is64 = __syncthreads_and(odd_zero);
    for (int b = tid; b < BB; b += nthreads) {
        const int tv = is64 ? (int)raw[2 * b] : (int)raw[b];
        if (tv == t && (b & bmask) == bval)
            s_idx[atomicAdd(s_cnt, 1)] = b;
    }
    __syncthreads();
    return *s_cnt;
}

// ---------------------------------------------------------------------------
// fc1 partial (R13 proven version): grid (T, 2 h-tiles of 256, 2 d-halves of
// 256). 128 threads, thread owns 2 h cols x 16 sample rows. float2 weight
// stream with 8-deep register prefetch. d-half 0 folds in bias; relu in fc2.
// Each block processes ALL samples of its task (no cross-block split), so
// list order is irrelevant here.
// ---------------------------------------------------------------------------
__global__ __launch_bounds__(128) void fc1_kernel(
    const float* __restrict__ xs,
    const unsigned int* __restrict__ task_raw,
    const float* __restrict__ w1,
    const float* __restrict__ b1,
    float* __restrict__ gA,
    float* __restrict__ gB)
{
    const int t = blockIdx.x;
    const int h0 = blockIdx.y * 256;
    const int d0 = blockIdx.z * 256;
    const int tid = threadIdx.x;

    __shared__ __align__(16) float s_x[16][256];
    __shared__ int s_idx[128];
    __shared__ int s_cnt;

    const int cnt = build_task_list(task_raw, t, tid, 128, 0, 0, s_idx, &s_cnt);
    if (cnt == 0) return;

    const float* wbase = w1 + (size_t)t * DD * HH + (size_t)d0 * HH + h0 + tid * 2;
    float2 bias = make_float2(0.0f, 0.0f);
    if (d0 == 0)
        bias = *(const float2*)(b1 + (size_t)t * HH + h0 + tid * 2);
    float* gout = (d0 == 0) ? gA : gB;

    for (int c0 = 0; c0 < cnt; c0 += 16) {
        const int m = min(16, cnt - c0);
        // stage x rows for this d-half: 256 floats per row, float2 per thread
        #pragma unroll
        for (int r = 0; r < 16; r++) {
            float2 v = make_float2(0.0f, 0.0f);
            if (r < m)
                v = *(const float2*)(xs + (size_t)s_idx[c0 + r] * DD + d0 + tid * 2);
            *(float2*)&s_x[r][tid * 2] = v;
        }
        __syncthreads();

        float2 acc[16];
        #pragma unroll
        for (int r = 0; r < 16; r++) { acc[r].x = 0.0f; acc[r].y = 0.0f; }

        // software-pipelined weight stream: 8 float2 loads in flight
        float2 wreg[8];
        #pragma unroll
        for (int k = 0; k < 8; k++)
            wreg[k] = *(const float2*)(wbase + (size_t)k * HH);

        for (int d = 0; d < 256; d += 8) {
            float2 wc[8];
            #pragma unroll
            for (int k = 0; k < 8; k++) wc[k] = wreg[k];
            if (d + 8 < 256) {
                #pragma unroll
                for (int k = 0; k < 8; k++)
                    wreg[k] = *(const float2*)(wbase + (size_t)(d + 8 + k) * HH);
            }
            #pragma unroll
            for (int k = 0; k < 8; k++) {
                #pragma unroll
                for (int r = 0; r < 16; r++) {
                    const float x = s_x[r][d + k];
                    acc[r].x = fmaf(x, wc[k].x, acc[r].x);
                    acc[r].y = fmaf(x, wc[k].y, acc[r].y);
                }
            }
        }

        for (int r = 0; r < m; r++) {
            const int b = s_idx[c0 + r];
            float2 v;
            v.x = acc[r].x + bias.x;
            v.y = acc[r].y + bias.y;
            *(float2*)(gout + (size_t)b * HH + h0 + tid * 2) = v;
        }
        __syncthreads();
    }
}

// ---------------------------------------------------------------------------
// JAX Threefry-2x32, partitionable convention (verified R9):
// bits[i] = w0 ^ w1 of threefry2x32(k0=0, k1=1, x0=0, x1=i)
// ---------------------------------------------------------------------------
__device__ __forceinline__ uint32_t rotl32(uint32_t x, int r) {
    return (x << r) | (x >> (32 - r));
}

__device__ uint2 threefry2x32(uint32_t k0, uint32_t k1, uint32_t x0, uint32_t x1)
{
    const uint32_t ks0 = k0, ks1 = k1, ks2 = k0 ^ k1 ^ 0x1BD11BDAu;
    x0 += ks0; x1 += ks1;
    x0 += x1; x1 = rotl32(x1, 13); x1 ^= x0;
    x0 += x1; x1 = rotl32(x1, 15); x1 ^= x0;
    x0 += x1; x1 = rotl32(x1, 26); x1 ^= x0;
    x0 += x1; x1 = rotl32(x1,  6); x1 ^= x0;
    x0 += ks1; x1 += ks2 + 1u;
    x0 += x1; x1 = rotl32(x1, 17); x1 ^= x0;
    x0 += x1; x1 = rotl32(x1, 29); x1 ^= x0;
    x0 += x1; x1 = rotl32(x1, 16); x1 ^= x0;
    x0 += x1; x1 = rotl32(x1, 24); x1 ^= x0;
    x0 += ks2; x1 += ks0 + 2u;
    x0 += x1; x1 = rotl32(x1, 13); x1 ^= x0;
    x0 += x1; x1 = rotl32(x1, 15); x1 ^= x0;
    x0 += x1; x1 = rotl32(x1, 26); x1 ^= x0;
    x0 += x1; x1 = rotl32(x1,  6); x1 ^= x0;
    x0 += ks0; x1 += ks1 + 3u;
    x0 += x1; x1 = rotl32(x1, 17); x1 ^= x0;
    x0 += x1; x1 = rotl32(x1, 29); x1 ^= x0;
    x0 += x1; x1 = rotl32(x1, 16); x1 ^= x0;
    x0 += x1; x1 = rotl32(x1, 24); x1 ^= x0;
    x0 += ks1; x1 += ks2 + 4u;
    x0 += x1; x1 = rotl32(x1, 13); x1 ^= x0;
    x0 += x1; x1 = rotl32(x1, 15); x1 ^= x0;
    x0 += x1; x1 = rotl32(x1, 26); x1 ^= x0;
    x0 += x1; x1 = rotl32(x1,  6); x1 ^= x0;
    x0 += ks2; x1 += ks0 + 5u;
    return make_uint2(x0, x1);
}

__device__ __forceinline__ uint32_t jax_random_bits(uint32_t i)
{
    uint2 r = threefry2x32(0u, 1u, 0u, i);
    return r.x ^ r.y;
}

// ---------------------------------------------------------------------------
// fc2 + log_softmax + gumbel categorical + log_prob + entropy.
// grid (T, 4): block (t, q) owns samples of task t with (b & 3) == q —
// a partition by sample identity, immune to list-order nondeterminism.
// One warp per sample. h = relu(hA + hB). Per-lane acc[18] + interleaved
// butterflies (bit-identical to R13's per-a serial reduction).
// ---------------------------------------------------------------------------
__global__ __launch_bounds__(256) void fc2_kernel(
    const unsigned int* __restrict__ task_raw,
    const float* __restrict__ w2,
    const float* __restrict__ b2,
    const float* __restrict__ hA,
    const float* __restrict__ hB,
    float* __restrict__ out)
{
    const int t = blockIdx.x;
    const int q = blockIdx.y;
    const int tid = threadIdx.x;

    __shared__ __align__(16) float s_w[HH * AA];   // 36 KB
    __shared__ float s_b[AA];
    __shared__ int s_idx[128];
    __shared__ int s_cnt;

    // stage w2[t] as float4 (HH*AA/4 = 2304 = 9 * 256 exactly)
    const float4* w2t = (const float4*)(w2 + (size_t)t * HH * AA);
    float4* swv = (float4*)s_w;
    #pragma unroll
    for (int i = 0; i < 9; i++)
        swv[tid + i * 256] = w2t[tid + i * 256];
    if (tid < AA) s_b[tid] = b2[t * AA + tid];
    // only samples with (b & 3) == q in this block's list
    const int cnt = build_task_list(task_raw, t, tid, 256, 3, q, s_idx, &s_cnt);

    const int warp = tid >> 5;
    const int l = tid & 31;

    for (int s = warp; s < cnt; s += 8) {
        const int b = s_idx[s];
        float hreg[16];
        #pragma unroll
        for (int i = 0; i < 16; i++) {
            const size_t off = (size_t)b * HH + i * 32 + l;
            hreg[i] = fmaxf(hA[off] + hB[off], 0.0f);
        }

        // per-lane partials for all 18 actions (i ascending == R13 order)
        float acc[AA];
        #pragma unroll
        for (int a = 0; a < AA; a++) acc[a] = 0.0f;
        #pragma unroll
        for (int i = 0; i < 16; i++) {
            const float x = hreg[i];
            const float* wr = &s_w[(i * 32 + l) * AA];
            #pragma unroll
            for (int a = 0; a < AA; a++)
                acc[a] = fmaf(x, wr[a], acc[a]);
        }
        // 18 interleaved butterfly reductions
        #pragma unroll
        for (int off = 16; off > 0; off >>= 1) {
            #pragma unroll
            for (int a = 0; a < AA; a++)
                acc[a] += __shfl_xor_sync(0xffffffffu, acc[a], off);
        }
        float logit = -INFINITY;
        #pragma unroll
        for (int a = 0; a < AA; a++)
            if (l == a) logit = acc[a] + s_b[a];

        // log_softmax
        float mx = logit;
        #pragma unroll
        for (int off = 16; off > 0; off >>= 1)
            mx = fmaxf(mx, __shfl_xor_sync(0xffffffffu, mx, off));
        float ex = (l < AA) ? expf(logit - mx) : 0.0f;
        float sum = ex;
        #pragma unroll
        for (int off = 16; off > 0; off >>= 1)
            sum += __shfl_xor_sync(0xffffffffu, sum, off);
        const float lse = mx + logf(sum);
        const float logp = logit - lse;

        // entropy
        float ent = (l < AA) ? (-expf(logp) * logp) : 0.0f;
        #pragma unroll
        for (int off = 16; off > 0; off >>= 1)
            ent += __shfl_xor_sync(0xffffffffu, ent, off);

        // gumbel noise (JAX partitionable threefry, XOR convention)
        float y = -INFINITY;
        if (l < AA) {
            const uint32_t bits = jax_random_bits((uint32_t)(b * AA + l));
            const float f = __uint_as_float((bits >> 9) | 0x3f800000u) - 1.0f;
            const float TINY = 1.17549435e-38f;
            const float u = fmaxf(TINY, f * (1.0f - TINY) + TINY);
            const float g = -logf(-logf(u));
            y = logit + g;
        }
        // argmax, first-index tiebreak
        int bi = l;
        #pragma unroll
        for (int off = 16; off > 0; off >>= 1) {
            const float oy = __shfl_xor_sync(0xffffffffu, y, off);
            const int ob = __shfl_xor_sync(0xffffffffu, bi, off);
            if (oy > y || (oy == y && ob < bi)) { y = oy; bi = ob; }
        }
        const float lp_action = __shfl_sync(0xffffffffu, logp, bi);

        if (l == 0) {
            out[b] = (float)bi;
            out[BB + b] = lp_action;
            out[2 * BB + b] = ent;
        }
    }
}

extern "C" void kernel_launch(void* const* d_in, const int* in_sizes, int n_in,
                              void* d_out, int out_size)
{
    // Map inputs by element count (all distinct) — immune to metadata ordering.
    const float* xs = nullptr;
    const unsigned int* task_raw = nullptr;
    const float* w1 = nullptr;
    const float* b1 = nullptr;
    const float* w2 = nullptr;
    const float* b2 = nullptr;
    for (int i = 0; i < n_in; i++) {
        switch (in_sizes[i]) {
            case BB * DD:        xs = (const float*)d_in[i]; break;
            case BB:             task_raw = (const unsigned int*)d_in[i]; break;
            case TT * DD * HH:   w1 = (const float*)d_in[i]; break;
            case TT * HH:        b1 = (const float*)d_in[i]; break;
            case TT * HH * AA:   w2 = (const float*)d_in[i]; break;
            case TT * AA:        b2 = (const float*)d_in[i]; break;
            default: break;
        }
    }
    float* out = (float*)d_out;

    float *hA, *hB;
    cudaGetSymbolAddress((void**)&hA, g_hA);
    cudaGetSymbolAddress((void**)&hB, g_hB);

    dim3 g1(TT, 2, 2);
    fc1_kernel<<<g1, 128>>>(xs, task_raw, w1, b1, hA, hB);
    dim3 g2(TT, 4);
    fc2_kernel<<<g2, 256>>>(task_raw, w2, b2, hA, hB, out);
}